// round 2
// baseline (speedup 1.0000x reference)
#include <cuda_runtime.h>
#include <cstdint>

#define Bc   128
#define Mc   512
#define Wc   128
#define Rc   4
#define INc  1024
#define NOUT 919
#define DELTA 1e-6f

// ---------------- scratch (device globals; no allocations) ----------------
__device__ float g_Wcat[NOUT * INc];
__device__ float g_bcat[NOUT];
__device__ float g_C[Bc * NOUT];

__device__ float g_rk[Bc * Rc * Wc];   // tanh(read keys)
__device__ float g_rs[Bc * Rc];        // softplus(read strengths)
__device__ float g_wk[Bc * Wc];        // tanh(write key)
__device__ float g_ws[Bc];             // softplus(write strength)
__device__ float g_ev[Bc * Wc];        // sigmoid(erase)
__device__ float g_wv[Bc * Wc];        // tanh(write vector)
__device__ float g_fg[Bc * Rc];        // sigmoid(free gates)
__device__ float g_ag[Bc];             // sigmoid(alloc gate)
__device__ float g_wg[Bc];             // sigmoid(write gate)
__device__ float g_rm[Bc * Rc * 3];    // raw read modes

__device__ float g_alloc[Bc * Mc];
__device__ float g_mnorm[Bc * Mc];     // ||memory row||
__device__ float g_wdot [Bc * Mc];     // memory row . write key
__device__ float g_ww   [Bc * Mc];     // final write weights
__device__ float g_nnorm[Bc * Mc];     // ||mem_new row||
__device__ float g_rdot [Bc * Rc * Mc];// mem_new row . read key r
__device__ float g_cw   [Bc * Rc * Mc];
__device__ float g_fwd  [Bc * Rc * Mc];
__device__ float g_bwd  [Bc * Rc * Mc];

// ---------------- helpers ----------------
__device__ __forceinline__ float wsum(float v) {
    v += __shfl_xor_sync(0xffffffffu, v, 16);
    v += __shfl_xor_sync(0xffffffffu, v, 8);
    v += __shfl_xor_sync(0xffffffffu, v, 4);
    v += __shfl_xor_sync(0xffffffffu, v, 2);
    v += __shfl_xor_sync(0xffffffffu, v, 1);
    return v;
}
__device__ __forceinline__ float softplusf(float v) {
    return fmaxf(v, 0.f) + log1pf(expf(-fabsf(v)));
}
__device__ __forceinline__ float sigf(float v) { return 1.f / (1.f + expf(-v)); }

struct WPtrs { const float* W[10]; const float* bia[10]; };

// ---------------- K0: concat weight matrices ----------------
__global__ void k0_concat(WPtrs p) {
    const int offs[11] = {0, 512, 516, 644, 645, 773, 901, 905, 906, 907, 919};
    int row = blockIdx.x;
    int seg = 0;
#pragma unroll
    for (int s = 0; s < 10; s++) if (row >= offs[s + 1]) seg = s + 1;
    int off = offs[seg];
    const float4* src = (const float4*)(p.W[seg] + (size_t)(row - off) * INc);
    float4* dst = (float4*)(g_Wcat + (size_t)row * INc);
    dst[threadIdx.x] = src[threadIdx.x];          // 256 threads x float4 = 1024 floats
    if (threadIdx.x == 0) g_bcat[row] = p.bia[seg][row - off];
}

// ---------------- K1: GEMM C[128,919] = x[128,1024] * Wcat^T ----------------
__global__ __launch_bounds__(256) void k1_gemm(const float* __restrict__ A) {
    __shared__ float As[32][33];
    __shared__ float Bs[32][33];
    int tx = threadIdx.x, ty = threadIdx.y;      // 16x16
    int b0 = blockIdx.y * 32, o0 = blockIdx.x * 32;
    float acc00 = 0.f, acc01 = 0.f, acc10 = 0.f, acc11 = 0.f;
    int t = ty * 16 + tx;
    for (int k0 = 0; k0 < INc; k0 += 32) {
#pragma unroll
        for (int i = 0; i < 4; i++) {
            int e = t + i * 256;
            int r = e >> 5, kk = e & 31;
            As[r][kk] = A[(size_t)(b0 + r) * INc + k0 + kk];
            Bs[r][kk] = (o0 + r < NOUT) ? g_Wcat[(size_t)(o0 + r) * INc + k0 + kk] : 0.f;
        }
        __syncthreads();
#pragma unroll
        for (int kk = 0; kk < 32; kk++) {
            float a0 = As[ty * 2][kk], a1 = As[ty * 2 + 1][kk];
            float w0 = Bs[tx * 2][kk], w1 = Bs[tx * 2 + 1][kk];
            acc00 = fmaf(a0, w0, acc00); acc01 = fmaf(a0, w1, acc01);
            acc10 = fmaf(a1, w0, acc10); acc11 = fmaf(a1, w1, acc11);
        }
        __syncthreads();
    }
    int bb = b0 + ty * 2, oo = o0 + tx * 2;
    if (oo     < NOUT) { g_C[bb * NOUT + oo    ] = acc00; g_C[(bb + 1) * NOUT + oo    ] = acc10; }
    if (oo + 1 < NOUT) { g_C[bb * NOUT + oo + 1] = acc01; g_C[(bb + 1) * NOUT + oo + 1] = acc11; }
}

// ---------------- K1b: bias + activation + scatter ----------------
__global__ void k1b_act() {
    int id = blockIdx.x * 256 + threadIdx.x;
    if (id >= Bc * NOUT) return;
    int b = id / NOUT, o = id % NOUT;
    float v = g_C[id] + g_bcat[o];
    if      (o < 512) g_rk[b * 512 + o]        = tanhf(v);
    else if (o < 516) g_rs[b * 4 + o - 512]    = softplusf(v);
    else if (o < 644) g_wk[b * 128 + o - 516]  = tanhf(v);
    else if (o == 644) g_ws[b]                 = softplusf(v);
    else if (o < 773) g_ev[b * 128 + o - 645]  = sigf(v);
    else if (o < 901) g_wv[b * 128 + o - 773]  = tanhf(v);
    else if (o < 905) g_fg[b * 4 + o - 901]    = sigf(v);
    else if (o == 905) g_ag[b]                 = sigf(v);
    else if (o == 906) g_wg[b]                 = sigf(v);
    else              g_rm[b * 12 + o - 907]   = v;
}

// ---------------- K3: usage update + sort + allocation ----------------
__global__ __launch_bounds__(512) void k3_alloc(const float* __restrict__ usage_v,
                                               const float* __restrict__ wwts,
                                               const float* __restrict__ rw_old) {
    int b = blockIdx.x, tid = threadIdx.x;
    __shared__ float key[512];
    __shared__ int   idx[512];
    __shared__ float pr[512];
    float u0 = usage_v[b * Mc + tid];
    float wv = wwts[b * Mc + tid];
    float us = u0 + (1.f - u0) * wv;
    float psi = 1.f;
#pragma unroll
    for (int r = 0; r < Rc; r++)
        psi *= 1.f - g_fg[b * Rc + r] * rw_old[((size_t)b * Rc + r) * Mc + tid];
    us *= psi;
    float u = DELTA + (1.f - DELTA) * us;
    key[tid] = u; idx[tid] = tid;
    __syncthreads();
    // bitonic sort ascending
    for (int k = 2; k <= 512; k <<= 1)
        for (int j = k >> 1; j > 0; j >>= 1) {
            int ixj = tid ^ j;
            if (ixj > tid) {
                bool up = (tid & k) == 0;
                float a = key[tid], c = key[ixj];
                if ((a > c) == up) {
                    key[tid] = c; key[ixj] = a;
                    int t2 = idx[tid]; idx[tid] = idx[ixj]; idx[ixj] = t2;
                }
            }
            __syncthreads();
        }
    // inclusive multiplicative scan -> exclusive
    pr[tid] = key[tid];
    __syncthreads();
    for (int off = 1; off < 512; off <<= 1) {
        float v = (tid >= off) ? pr[tid - off] : 1.f;
        __syncthreads();
        pr[tid] *= v;
        __syncthreads();
    }
    float excl = (tid == 0) ? 1.f : pr[tid - 1];
    float as = (1.f - key[tid]) * excl;
    g_alloc[b * Mc + idx[tid]] = as;
}

// ---------------- K4: old memory row norms + write-key dots ----------------
__global__ __launch_bounds__(256) void k4_mstats(const float* __restrict__ mem) {
    int wid = blockIdx.x * 8 + (threadIdx.x >> 5);
    int lane = threadIdx.x & 31;
    int b = wid >> 9, m = wid & 511;
    const float4 v = ((const float4*)(mem + ((size_t)b * Mc + m) * Wc))[lane];
    const float4 kk = ((const float4*)(g_wk + b * Wc))[lane];
    float ss = v.x * v.x + v.y * v.y + v.z * v.z + v.w * v.w;
    float dd = v.x * kk.x + v.y * kk.y + v.z * kk.z + v.w * kk.w;
    ss = wsum(ss); dd = wsum(dd);
    if (lane == 0) { g_mnorm[b * Mc + m] = sqrtf(ss); g_wdot[b * Mc + m] = dd; }
}

// ---------------- K5: write content softmax + final write weights ----------------
__global__ __launch_bounds__(512) void k5_ww() {
    int b = blockIdx.x, tid = threadIdx.x;
    __shared__ float red[512];
    float kv = 0.f;
    if (tid < 128) { float t = g_wk[b * Wc + tid]; kv = t * t; }
    red[tid] = kv; __syncthreads();
    for (int s = 256; s > 0; s >>= 1) { if (tid < s) red[tid] += red[tid + s]; __syncthreads(); }
    float bn = sqrtf(red[0]) + DELTA;
    __syncthreads();
    float an = g_mnorm[b * Mc + tid] + DELTA;
    float d = g_wdot[b * Mc + tid] / (128.f * bn * an + DELTA);
    float l = d * g_ws[b];
    red[tid] = l; __syncthreads();
    for (int s = 256; s > 0; s >>= 1) { if (tid < s) red[tid] = fmaxf(red[tid], red[tid + s]); __syncthreads(); }
    float mx = red[0]; __syncthreads();
    float e = expf(l - mx);
    red[tid] = e; __syncthreads();
    for (int s = 256; s > 0; s >>= 1) { if (tid < s) red[tid] += red[tid + s]; __syncthreads(); }
    float wcw = e / red[0];
    float ag = g_ag[b], wg = g_wg[b];
    g_ww[b * Mc + tid] = wg * (ag * g_alloc[b * Mc + tid] + (1.f - ag) * wcw);
}

// ---------------- K6: mem_new row norms + read-key dots (mem_new recomputed) ----
__global__ __launch_bounds__(256) void k6_nstats(const float* __restrict__ mem) {
    int wid = blockIdx.x * 8 + (threadIdx.x >> 5);
    int lane = threadIdx.x & 31;
    int b = wid >> 9, m = wid & 511;
    const float4 v  = ((const float4*)(mem + ((size_t)b * Mc + m) * Wc))[lane];
    const float4 e4 = ((const float4*)(g_ev + b * Wc))[lane];
    const float4 w4 = ((const float4*)(g_wv + b * Wc))[lane];
    float t = g_ww[b * Mc + m];
    float4 nm;
    nm.x = fmaf(v.x, 1.f - t * e4.x, t * w4.x);
    nm.y = fmaf(v.y, 1.f - t * e4.y, t * w4.y);
    nm.z = fmaf(v.z, 1.f - t * e4.z, t * w4.z);
    nm.w = fmaf(v.w, 1.f - t * e4.w, t * w4.w);
    float ss = nm.x * nm.x + nm.y * nm.y + nm.z * nm.z + nm.w * nm.w;
    float dr[Rc];
#pragma unroll
    for (int r = 0; r < Rc; r++) {
        const float4 k4 = ((const float4*)(g_rk + ((size_t)b * Rc + r) * Wc))[lane];
        dr[r] = nm.x * k4.x + nm.y * k4.y + nm.z * k4.z + nm.w * k4.w;
    }
    ss = wsum(ss);
#pragma unroll
    for (int r = 0; r < Rc; r++) dr[r] = wsum(dr[r]);
    if (lane == 0) {
        g_nnorm[b * Mc + m] = sqrtf(ss);
#pragma unroll
        for (int r = 0; r < Rc; r++) g_rdot[((size_t)b * Rc + r) * Mc + m] = dr[r];
    }
}

// ---------------- K7: read content softmax ----------------
__global__ __launch_bounds__(512) void k7_cw() {
    int br = blockIdx.x;
    int b = br >> 2, r = br & 3;
    int tid = threadIdx.x;
    __shared__ float red[512];
    float kv = 0.f;
    if (tid < 128) { float t = g_rk[((size_t)b * Rc + r) * Wc + tid]; kv = t * t; }
    red[tid] = kv; __syncthreads();
    for (int s = 256; s > 0; s >>= 1) { if (tid < s) red[tid] += red[tid + s]; __syncthreads(); }
    float kn = sqrtf(red[0]) + DELTA;
    __syncthreads();
    float an = g_nnorm[b * Mc + tid] + DELTA;
    float d = g_rdot[((size_t)b * Rc + r) * Mc + tid] / (128.f * kn * an + DELTA);
    float l = d * g_rs[b * Rc + r];
    red[tid] = l; __syncthreads();
    for (int s = 256; s > 0; s >>= 1) { if (tid < s) red[tid] = fmaxf(red[tid], red[tid + s]); __syncthreads(); }
    float mx = red[0]; __syncthreads();
    float e = expf(l - mx);
    red[tid] = e; __syncthreads();
    for (int s = 256; s > 0; s >>= 1) { if (tid < s) red[tid] += red[tid + s]; __syncthreads(); }
    g_cw[((size_t)b * Rc + r) * Mc + tid] = e / red[0];
}

// ---------------- K8: streaming link update fused with fwd/bwd ----------------
// T[i,j] = (1-ww_i-ww_j)*link[i,j] + ww_i*p[j]   (0 on diagonal)
// fwd[r,i] = sum_j T[i,j]*rw[r,j] ;  bwd[r,j] += rw[r,i]*T[i,j]
__global__ __launch_bounds__(512, 1) void k8_link(const float* __restrict__ link,
                                                  const float* __restrict__ prec,
                                                  const float* __restrict__ rw_old) {
    int b = blockIdx.x;
    __shared__ float rw_s[Rc][Mc];
    __shared__ float ww_s[Mc];
    __shared__ float p_s[Mc];
    __shared__ float fwd_s[Rc][Mc];
    __shared__ float bwd_s[Rc][Mc];
    int tid = threadIdx.x;
    for (int e = tid; e < Rc * Mc; e += 512) {
        int r = e >> 9, m = e & 511;
        rw_s[r][m] = rw_old[((size_t)b * Rc + r) * Mc + m];
        fwd_s[r][m] = 0.f; bwd_s[r][m] = 0.f;
    }
    ww_s[tid] = g_ww[b * Mc + tid];
    p_s[tid]  = prec[b * Mc + tid];
    __syncthreads();

    int w = tid >> 5, lane = tid & 31;
    int h = w & 1;                 // column half
    int rg = w >> 1;               // row group
    int jbase = h * 256 + lane;

    float wwj[8], pj[8], rj0[8], rj1[8], rj2[8], rj3[8];
#pragma unroll
    for (int k = 0; k < 8; k++) {
        int j = jbase + 32 * k;
        wwj[k] = ww_s[j]; pj[k] = p_s[j];
        rj0[k] = rw_s[0][j]; rj1[k] = rw_s[1][j]; rj2[k] = rw_s[2][j]; rj3[k] = rw_s[3][j];
    }
    float bd0[8] = {}, bd1[8] = {}, bd2[8] = {}, bd3[8] = {};

    const float* lb = link + (size_t)b * Mc * Mc;
    for (int i = rg; i < Mc; i += 8) {
        const float* row = lb + (size_t)i * Mc + h * 256;
        float x[8];
#pragma unroll
        for (int k = 0; k < 8; k++) x[k] = row[lane + 32 * k];
        float wwi = ww_s[i];
        float c1 = 1.f - wwi;
        float ri0 = rw_s[0][i], ri1 = rw_s[1][i], ri2 = rw_s[2][i], ri3 = rw_s[3][i];
        float f0 = 0.f, f1 = 0.f, f2 = 0.f, f3 = 0.f;
#pragma unroll
        for (int k = 0; k < 8; k++) {
            float T = fmaf(c1 - wwj[k], x[k], wwi * pj[k]);
            if (jbase + 32 * k == i) T = 0.f;
            f0 = fmaf(T, rj0[k], f0); f1 = fmaf(T, rj1[k], f1);
            f2 = fmaf(T, rj2[k], f2); f3 = fmaf(T, rj3[k], f3);
            bd0[k] = fmaf(T, ri0, bd0[k]); bd1[k] = fmaf(T, ri1, bd1[k]);
            bd2[k] = fmaf(T, ri2, bd2[k]); bd3[k] = fmaf(T, ri3, bd3[k]);
        }
        f0 = wsum(f0); f1 = wsum(f1); f2 = wsum(f2); f3 = wsum(f3);
        if (lane == 0) {
            atomicAdd(&fwd_s[0][i], f0); atomicAdd(&fwd_s[1][i], f1);
            atomicAdd(&fwd_s[2][i], f2); atomicAdd(&fwd_s[3][i], f3);
        }
    }
#pragma unroll
    for (int k = 0; k < 8; k++) {
        int j = jbase + 32 * k;
        atomicAdd(&bwd_s[0][j], bd0[k]); atomicAdd(&bwd_s[1][j], bd1[k]);
        atomicAdd(&bwd_s[2][j], bd2[k]); atomicAdd(&bwd_s[3][j], bd3[k]);
    }
    __syncthreads();
    for (int e = tid; e < Rc * Mc; e += 512) {
        int r = e >> 9, m = e & 511;
        g_fwd[((size_t)b * Rc + r) * Mc + m] = fwd_s[r][m];
        g_bwd[((size_t)b * Rc + r) * Mc + m] = bwd_s[r][m];
    }
}

// ---------------- K9: read-mode mix + read vectors (mem_new recomputed) --------
__global__ __launch_bounds__(128) void k9_out(const float* __restrict__ mem,
                                              float* __restrict__ out) {
    int b = blockIdx.x;
    int wt = threadIdx.x;  // w index
    __shared__ float rwn[Rc][Mc];
    __shared__ float ww_s[Mc];
    __shared__ float ms[Rc][3];
    if (wt < Rc) {
        float a0 = g_rm[b * 12 + wt * 3 + 0];
        float a1 = g_rm[b * 12 + wt * 3 + 1];
        float a2 = g_rm[b * 12 + wt * 3 + 2];
        float mx = fmaxf(a0, fmaxf(a1, a2));
        float e0 = expf(a0 - mx), e1 = expf(a1 - mx), e2 = expf(a2 - mx);
        float s = e0 + e1 + e2;
        ms[wt][0] = e0 / s; ms[wt][1] = e1 / s; ms[wt][2] = e2 / s;
    }
    __syncthreads();
    for (int e = wt; e < Rc * Mc; e += 128) {
        int r = e >> 9, m = e & 511;
        size_t i = ((size_t)b * Rc + r) * Mc + m;
        rwn[r][m] = ms[r][0] * g_bwd[i] + ms[r][1] * g_fwd[i] + ms[r][2] * g_cw[i];
    }
    for (int m = wt; m < Mc; m += 128) ww_s[m] = g_ww[b * Mc + m];
    __syncthreads();
    float evw = g_ev[b * Wc + wt], wvw = g_wv[b * Wc + wt];
    float a0 = 0.f, a1 = 0.f, a2 = 0.f, a3 = 0.f;
    const float* mb = mem + (size_t)b * Mc * Wc;
#pragma unroll 8
    for (int m = 0; m < Mc; m++) {
        float x = mb[(size_t)m * Wc + wt];
        float t = ww_s[m];
        float nm = fmaf(x, 1.f - t * evw, t * wvw);
        a0 = fmaf(rwn[0][m], nm, a0);
        a1 = fmaf(rwn[1][m], nm, a1);
        a2 = fmaf(rwn[2][m], nm, a2);
        a3 = fmaf(rwn[3][m], nm, a3);
    }
    out[((size_t)b * Rc + 0) * Wc + wt] = a0;
    out[((size_t)b * Rc + 1) * Wc + wt] = a1;
    out[((size_t)b * Rc + 2) * Wc + wt] = a2;
    out[((size_t)b * Rc + 3) * Wc + wt] = a3;
}

// ---------------- launch ----------------
extern "C" void kernel_launch(void* const* d_in, const int* in_sizes, int n_in,
                              void* d_out, int out_size) {
    const float* x        = (const float*)d_in[0];
    const float* memory   = (const float*)d_in[1];
    const float* link     = (const float*)d_in[2];
    const float* prec     = (const float*)d_in[3];
    const float* rw_old   = (const float*)d_in[4];
    const float* wwts     = (const float*)d_in[5];
    const float* usage_v  = (const float*)d_in[6];

    WPtrs p;
    for (int s = 0; s < 10; s++) {
        p.W[s]   = (const float*)d_in[7 + 2 * s];
        p.bia[s] = (const float*)d_in[8 + 2 * s];
    }
    float* out = (float*)d_out;

    k0_concat<<<NOUT, 256>>>(p);
    k1_gemm<<<dim3((NOUT + 31) / 32, Bc / 32), dim3(16, 16)>>>(x);
    k1b_act<<<(Bc * NOUT + 255) / 256, 256>>>();
    k3_alloc<<<Bc, 512>>>(usage_v, wwts, rw_old);
    k4_mstats<<<(Bc * Mc) / 8, 256>>>(memory);
    k5_ww<<<Bc, 512>>>();
    k6_nstats<<<(Bc * Mc) / 8, 256>>>(memory);
    k7_cw<<<Bc * Rc, 512>>>();
    k8_link<<<Bc, 512>>>(link, prec, rw_old);
    k9_out<<<Bc, 128>>>(memory, out);
}

// round 3
// speedup vs baseline: 1.3237x; 1.3237x over previous
#include <cuda_runtime.h>
#include <cstdint>

#define Bc   128
#define Mc   512
#define Wc   128
#define Rc   4
#define INc  1024
#define NOUT 919
#define DELTA 1e-6f
#define NCH  4          // k8 row chunks per batch
#define CHR  128        // rows per chunk

// ---------------- scratch (device globals; no allocations) ----------------
__device__ float g_Wcat[NOUT * INc];
__device__ float g_bcat[NOUT];

__device__ float g_rk[Bc * Rc * Wc];   // tanh(read keys)
__device__ float g_rs[Bc * Rc];        // softplus(read strengths)
__device__ float g_wk[Bc * Wc];        // tanh(write key)
__device__ float g_ws[Bc];             // softplus(write strength)
__device__ float g_ev[Bc * Wc];        // sigmoid(erase)
__device__ float g_wv[Bc * Wc];        // tanh(write vector)
__device__ float g_fg[Bc * Rc];        // sigmoid(free gates)
__device__ float g_ag[Bc];             // sigmoid(alloc gate)
__device__ float g_wg[Bc];             // sigmoid(write gate)
__device__ float g_rm[Bc * Rc * 3];    // raw read modes

__device__ float g_alloc[Bc * Mc];
__device__ float g_mnorm[Bc * Mc];
__device__ float g_wdot [Bc * Mc];
__device__ float g_ww   [Bc * Mc];
__device__ float g_nnorm[Bc * Mc];
__device__ float g_rdot [Bc * Rc * Mc];
__device__ float g_cw   [Bc * Rc * Mc];
__device__ float g_fwd  [Bc * Rc * Mc];
__device__ float g_bwdp [NCH * Bc * Rc * Mc];   // per-chunk bwd partials

// ---------------- helpers ----------------
__device__ __forceinline__ float wsum(float v) {
    v += __shfl_xor_sync(0xffffffffu, v, 16);
    v += __shfl_xor_sync(0xffffffffu, v, 8);
    v += __shfl_xor_sync(0xffffffffu, v, 4);
    v += __shfl_xor_sync(0xffffffffu, v, 2);
    v += __shfl_xor_sync(0xffffffffu, v, 1);
    return v;
}
__device__ __forceinline__ float wmaxr(float v) {
    v = fmaxf(v, __shfl_xor_sync(0xffffffffu, v, 16));
    v = fmaxf(v, __shfl_xor_sync(0xffffffffu, v, 8));
    v = fmaxf(v, __shfl_xor_sync(0xffffffffu, v, 4));
    v = fmaxf(v, __shfl_xor_sync(0xffffffffu, v, 2));
    v = fmaxf(v, __shfl_xor_sync(0xffffffffu, v, 1));
    return v;
}
__device__ __forceinline__ float softplusf(float v) {
    return fmaxf(v, 0.f) + log1pf(expf(-fabsf(v)));
}
__device__ __forceinline__ float sigf(float v) { return 1.f / (1.f + expf(-v)); }

struct WPtrs { const float* W[10]; const float* bia[10]; };

// ---------------- K0: concat weight matrices ----------------
__global__ void k0_concat(WPtrs p) {
    const int offs[11] = {0, 512, 516, 644, 645, 773, 901, 905, 906, 907, 919};
    int row = blockIdx.x;
    int seg = 0;
#pragma unroll
    for (int s = 0; s < 10; s++) if (row >= offs[s + 1]) seg = s + 1;
    int off = offs[seg];
    const float4* src = (const float4*)(p.W[seg] + (size_t)(row - off) * INc);
    float4* dst = (float4*)(g_Wcat + (size_t)row * INc);
    dst[threadIdx.x] = src[threadIdx.x];
    if (threadIdx.x == 0) g_bcat[row] = p.bia[seg][row - off];
}

// ---------------- activation scatter (fused into GEMM epilogue) ----------------
__device__ __forceinline__ void store_act(int b, int o, float v) {
    if (o >= NOUT) return;
    v += g_bcat[o];
    if      (o < 512)  g_rk[b * 512 + o]       = tanhf(v);
    else if (o < 516)  g_rs[b * 4 + o - 512]   = softplusf(v);
    else if (o < 644)  g_wk[b * 128 + o - 516] = tanhf(v);
    else if (o == 644) g_ws[b]                 = softplusf(v);
    else if (o < 773)  g_ev[b * 128 + o - 645] = sigf(v);
    else if (o < 901)  g_wv[b * 128 + o - 773] = tanhf(v);
    else if (o < 905)  g_fg[b * 4 + o - 901]   = sigf(v);
    else if (o == 905) g_ag[b]                 = sigf(v);
    else if (o == 906) g_wg[b]                 = sigf(v);
    else               g_rm[b * 12 + o - 907]  = v;
}

// ---------------- K1: GEMM + fused activations ----------------
__global__ __launch_bounds__(256) void k1_gemm(const float* __restrict__ A) {
    __shared__ float As[32][33];
    __shared__ float Bs[32][33];
    int tx = threadIdx.x, ty = threadIdx.y;      // 16x16
    int b0 = blockIdx.y * 32, o0 = blockIdx.x * 32;
    float acc00 = 0.f, acc01 = 0.f, acc10 = 0.f, acc11 = 0.f;
    int t  = ty * 16 + tx;
    int lr = t >> 3, lc = (t & 7) * 4;           // float4 loads: 32 rows x 8 quads
    for (int k0 = 0; k0 < INc; k0 += 32) {
        float4 a4 = *(const float4*)(A + (size_t)(b0 + lr) * INc + k0 + lc);
        float4 b4;
        if (o0 + lr < NOUT)
            b4 = *(const float4*)(g_Wcat + (size_t)(o0 + lr) * INc + k0 + lc);
        else
            b4 = make_float4(0.f, 0.f, 0.f, 0.f);
        As[lr][lc] = a4.x; As[lr][lc + 1] = a4.y; As[lr][lc + 2] = a4.z; As[lr][lc + 3] = a4.w;
        Bs[lr][lc] = b4.x; Bs[lr][lc + 1] = b4.y; Bs[lr][lc + 2] = b4.z; Bs[lr][lc + 3] = b4.w;
        __syncthreads();
#pragma unroll
        for (int kk = 0; kk < 32; kk++) {
            float a0 = As[ty * 2][kk], a1 = As[ty * 2 + 1][kk];
            float w0 = Bs[tx * 2][kk], w1 = Bs[tx * 2 + 1][kk];
            acc00 = fmaf(a0, w0, acc00); acc01 = fmaf(a0, w1, acc01);
            acc10 = fmaf(a1, w0, acc10); acc11 = fmaf(a1, w1, acc11);
        }
        __syncthreads();
    }
    int bb = b0 + ty * 2, oo = o0 + tx * 2;
    store_act(bb,     oo,     acc00);
    store_act(bb,     oo + 1, acc01);
    store_act(bb + 1, oo,     acc10);
    store_act(bb + 1, oo + 1, acc11);
}

// ---------------- K3: usage update + packed bitonic sort + shfl scan ----------------
__global__ __launch_bounds__(512) void k3_alloc(const float* __restrict__ usage_v,
                                               const float* __restrict__ wwts,
                                               const float* __restrict__ rw_old) {
    int b = blockIdx.x, tid = threadIdx.x;
    int lane = tid & 31, w = tid >> 5;
    __shared__ unsigned long long sv[512];
    __shared__ float wt_[16], wp_[16];

    float u0 = usage_v[b * Mc + tid];
    float wv = wwts[b * Mc + tid];
    float us = u0 + (1.f - u0) * wv;
    float psi = 1.f;
#pragma unroll
    for (int r = 0; r < Rc; r++)
        psi *= 1.f - g_fg[b * Rc + r] * rw_old[((size_t)b * Rc + r) * Mc + tid];
    us *= psi;
    float u = DELTA + (1.f - DELTA) * us;   // > 0, so float bits order-preserving

    unsigned long long v = ((unsigned long long)__float_as_uint(u) << 32) | (unsigned)tid;

    for (int k = 2; k <= 512; k <<= 1) {
        for (int j = k >> 1; j >= 32; j >>= 1) {
            sv[tid] = v;
            __syncthreads();
            unsigned long long o = sv[tid ^ j];
            bool up = (tid & k) == 0;
            bool keepmin = ((tid & j) == 0) == up;
            v = (keepmin == (v < o)) ? v : o;
            __syncthreads();
        }
        int j0 = (k >> 1 < 16) ? (k >> 1) : 16;
        for (int j = j0; j >= 1; j >>= 1) {
            unsigned long long o = __shfl_xor_sync(0xffffffffu, v, j);
            bool up = (tid & k) == 0;
            bool keepmin = ((tid & j) == 0) == up;
            v = (keepmin == (v < o)) ? v : o;
        }
    }

    float su = __uint_as_float((unsigned)(v >> 32));
    // inclusive multiplicative warp scan
    float x = su;
#pragma unroll
    for (int off = 1; off < 32; off <<= 1) {
        float y = __shfl_up_sync(0xffffffffu, x, off);
        if (lane >= off) x *= y;
    }
    if (lane == 31) wt_[w] = x;
    __syncthreads();
    if (tid < 16) {
        float xx = wt_[tid];
#pragma unroll
        for (int off = 1; off < 16; off <<= 1) {
            float y = __shfl_up_sync(0xffffu, xx, off);
            if (tid >= off) xx *= y;
        }
        float ex = __shfl_up_sync(0xffffu, xx, 1);
        wp_[tid] = (tid == 0) ? 1.f : ex;
    }
    __syncthreads();
    float exw = __shfl_up_sync(0xffffffffu, x, 1);
    float excl = ((lane == 0) ? 1.f : exw) * wp_[w];
    float as = (1.f - su) * excl;
    int sidx = (int)(v & 0xffffffffu);
    g_alloc[b * Mc + sidx] = as;
}

// ---------------- K4: old memory row norms + write-key dots ----------------
__global__ __launch_bounds__(256) void k4_mstats(const float* __restrict__ mem) {
    int wid = blockIdx.x * 8 + (threadIdx.x >> 5);
    int lane = threadIdx.x & 31;
    int b = wid >> 9, m = wid & 511;
    const float4 v = ((const float4*)(mem + ((size_t)b * Mc + m) * Wc))[lane];
    const float4 kk = ((const float4*)(g_wk + b * Wc))[lane];
    float ss = v.x * v.x + v.y * v.y + v.z * v.z + v.w * v.w;
    float dd = v.x * kk.x + v.y * kk.y + v.z * kk.z + v.w * kk.w;
    ss = wsum(ss); dd = wsum(dd);
    if (lane == 0) { g_mnorm[b * Mc + m] = sqrtf(ss); g_wdot[b * Mc + m] = dd; }
}

// ---------------- K5: write content softmax + final write weights ----------------
__global__ __launch_bounds__(512) void k5_ww() {
    int b = blockIdx.x, tid = threadIdx.x;
    int lane = tid & 31, w = tid >> 5;
    __shared__ float bn4[4], smax[16], ssum[16];
    float s = 0.f;
    if (tid < 128) { float t = g_wk[b * Wc + tid]; s = t * t; }
    s = wsum(s);
    if (tid < 128 && lane == 0) bn4[w] = s;
    __syncthreads();
    float bn = sqrtf(bn4[0] + bn4[1] + bn4[2] + bn4[3]) + DELTA;
    float an = g_mnorm[b * Mc + tid] + DELTA;
    float l = g_wdot[b * Mc + tid] / (128.f * bn * an + DELTA) * g_ws[b];
    float mx = wmaxr(l);
    if (lane == 0) smax[w] = mx;
    __syncthreads();
    float m2 = smax[0];
#pragma unroll
    for (int i = 1; i < 16; i++) m2 = fmaxf(m2, smax[i]);
    float e = expf(l - m2);
    float su = wsum(e);
    if (lane == 0) ssum[w] = su;
    __syncthreads();
    float tot = 0.f;
#pragma unroll
    for (int i = 0; i < 16; i++) tot += ssum[i];
    float wcw = e / tot;
    float ag = g_ag[b], wg = g_wg[b];
    g_ww[b * Mc + tid] = wg * (ag * g_alloc[b * Mc + tid] + (1.f - ag) * wcw);
}

// ---------------- K6: mem_new row norms + read-key dots ----------------
__global__ __launch_bounds__(256) void k6_nstats(const float* __restrict__ mem) {
    int wid = blockIdx.x * 8 + (threadIdx.x >> 5);
    int lane = threadIdx.x & 31;
    int b = wid >> 9, m = wid & 511;
    const float4 v  = ((const float4*)(mem + ((size_t)b * Mc + m) * Wc))[lane];
    const float4 e4 = ((const float4*)(g_ev + b * Wc))[lane];
    const float4 w4 = ((const float4*)(g_wv + b * Wc))[lane];
    float t = g_ww[b * Mc + m];
    float4 nm;
    nm.x = fmaf(v.x, 1.f - t * e4.x, t * w4.x);
    nm.y = fmaf(v.y, 1.f - t * e4.y, t * w4.y);
    nm.z = fmaf(v.z, 1.f - t * e4.z, t * w4.z);
    nm.w = fmaf(v.w, 1.f - t * e4.w, t * w4.w);
    float ss = nm.x * nm.x + nm.y * nm.y + nm.z * nm.z + nm.w * nm.w;
    float dr[Rc];
#pragma unroll
    for (int r = 0; r < Rc; r++) {
        const float4 k4 = ((const float4*)(g_rk + ((size_t)b * Rc + r) * Wc))[lane];
        dr[r] = nm.x * k4.x + nm.y * k4.y + nm.z * k4.z + nm.w * k4.w;
    }
    ss = wsum(ss);
#pragma unroll
    for (int r = 0; r < Rc; r++) dr[r] = wsum(dr[r]);
    if (lane == 0) {
        g_nnorm[b * Mc + m] = sqrtf(ss);
#pragma unroll
        for (int r = 0; r < Rc; r++) g_rdot[((size_t)b * Rc + r) * Mc + m] = dr[r];
    }
}

// ---------------- K7: read content softmax ----------------
__global__ __launch_bounds__(512) void k7_cw() {
    int br = blockIdx.x;
    int b = br >> 2, r = br & 3;
    int tid = threadIdx.x, lane = tid & 31, w = tid >> 5;
    __shared__ float kn4[4], smax[16], ssum[16];
    float s = 0.f;
    if (tid < 128) { float t = g_rk[((size_t)b * Rc + r) * Wc + tid]; s = t * t; }
    s = wsum(s);
    if (tid < 128 && lane == 0) kn4[w] = s;
    __syncthreads();
    float kn = sqrtf(kn4[0] + kn4[1] + kn4[2] + kn4[3]) + DELTA;
    float an = g_nnorm[b * Mc + tid] + DELTA;
    float l = g_rdot[((size_t)b * Rc + r) * Mc + tid] / (128.f * kn * an + DELTA) * g_rs[b * Rc + r];
    float mx = wmaxr(l);
    if (lane == 0) smax[w] = mx;
    __syncthreads();
    float m2 = smax[0];
#pragma unroll
    for (int i = 1; i < 16; i++) m2 = fmaxf(m2, smax[i]);
    float e = expf(l - m2);
    float su = wsum(e);
    if (lane == 0) ssum[w] = su;
    __syncthreads();
    float tot = 0.f;
#pragma unroll
    for (int i = 0; i < 16; i++) tot += ssum[i];
    g_cw[((size_t)b * Rc + r) * Mc + tid] = e / tot;
}

// ---------------- K8: streaming link update fused with fwd/bwd ----------------
// grid (NCH, Bc); each CTA does rows [c*128, c*128+128) x all 512 cols.
__global__ __launch_bounds__(256) void k8_link(const float* __restrict__ link,
                                               const float* __restrict__ prec,
                                               const float* __restrict__ rw_old) {
    int c = blockIdx.x, b = blockIdx.y;
    int i0 = c * CHR;
    __shared__ float rw_s[Rc][Mc];
    __shared__ float ww_s[Mc];
    __shared__ float p_s[Mc];
    __shared__ float fwd_s[Rc][CHR];
    __shared__ float bwd_s[Rc][Mc];
    int tid = threadIdx.x;
    for (int e = tid; e < Mc; e += 256) {
        ww_s[e] = g_ww[b * Mc + e];
        p_s[e]  = prec[b * Mc + e];
    }
    for (int e = tid; e < Rc * Mc; e += 256) {
        int r = e >> 9, m = e & 511;
        rw_s[r][m] = rw_old[((size_t)b * Rc + r) * Mc + m];
        bwd_s[r][m] = 0.f;
    }
    for (int e = tid; e < Rc * CHR; e += 256) {
        int r = e >> 7, i = e & (CHR - 1);
        fwd_s[r][i] = 0.f;
    }
    __syncthreads();

    int w = tid >> 5, lane = tid & 31;
    int h = w & 3;                  // column quarter (128 cols)
    int rg = w >> 2;                // row parity
    int jb = h * 128 + lane * 4;

    float4 wwj = *(float4*)&ww_s[jb];
    float4 pj  = *(float4*)&p_s[jb];
    float4 rj0 = *(float4*)&rw_s[0][jb];
    float4 rj1 = *(float4*)&rw_s[1][jb];
    float4 rj2 = *(float4*)&rw_s[2][jb];
    float4 rj3 = *(float4*)&rw_s[3][jb];
    float bd0x = 0, bd0y = 0, bd0z = 0, bd0w = 0;
    float bd1x = 0, bd1y = 0, bd1z = 0, bd1w = 0;
    float bd2x = 0, bd2y = 0, bd2z = 0, bd2w = 0;
    float bd3x = 0, bd3y = 0, bd3z = 0, bd3w = 0;

    const float* lb = link + (size_t)b * Mc * Mc;
    for (int i = i0 + rg; i < i0 + CHR; i += 2) {
        float4 x = *(const float4*)(lb + (size_t)i * Mc + jb);
        float wwi = ww_s[i];
        float c1 = 1.f - wwi;
        float T0 = fmaf(c1 - wwj.x, x.x, wwi * pj.x); if (jb     == i) T0 = 0.f;
        float T1 = fmaf(c1 - wwj.y, x.y, wwi * pj.y); if (jb + 1 == i) T1 = 0.f;
        float T2 = fmaf(c1 - wwj.z, x.z, wwi * pj.z); if (jb + 2 == i) T2 = 0.f;
        float T3 = fmaf(c1 - wwj.w, x.w, wwi * pj.w); if (jb + 3 == i) T3 = 0.f;
        float f0 = T0 * rj0.x + T1 * rj0.y + T2 * rj0.z + T3 * rj0.w;
        float f1 = T0 * rj1.x + T1 * rj1.y + T2 * rj1.z + T3 * rj1.w;
        float f2 = T0 * rj2.x + T1 * rj2.y + T2 * rj2.z + T3 * rj2.w;
        float f3 = T0 * rj3.x + T1 * rj3.y + T2 * rj3.z + T3 * rj3.w;
        float ri0 = rw_s[0][i], ri1 = rw_s[1][i], ri2 = rw_s[2][i], ri3 = rw_s[3][i];
        bd0x = fmaf(T0, ri0, bd0x); bd0y = fmaf(T1, ri0, bd0y); bd0z = fmaf(T2, ri0, bd0z); bd0w = fmaf(T3, ri0, bd0w);
        bd1x = fmaf(T0, ri1, bd1x); bd1y = fmaf(T1, ri1, bd1y); bd1z = fmaf(T2, ri1, bd1z); bd1w = fmaf(T3, ri1, bd1w);
        bd2x = fmaf(T0, ri2, bd2x); bd2y = fmaf(T1, ri2, bd2y); bd2z = fmaf(T2, ri2, bd2z); bd2w = fmaf(T3, ri2, bd2w);
        bd3x = fmaf(T0, ri3, bd3x); bd3y = fmaf(T1, ri3, bd3y); bd3z = fmaf(T2, ri3, bd3z); bd3w = fmaf(T3, ri3, bd3w);
        f0 = wsum(f0); f1 = wsum(f1); f2 = wsum(f2); f3 = wsum(f3);
        if (lane == 0) {
            atomicAdd(&fwd_s[0][i - i0], f0);
            atomicAdd(&fwd_s[1][i - i0], f1);
            atomicAdd(&fwd_s[2][i - i0], f2);
            atomicAdd(&fwd_s[3][i - i0], f3);
        }
    }
    atomicAdd(&bwd_s[0][jb], bd0x); atomicAdd(&bwd_s[0][jb + 1], bd0y);
    atomicAdd(&bwd_s[0][jb + 2], bd0z); atomicAdd(&bwd_s[0][jb + 3], bd0w);
    atomicAdd(&bwd_s[1][jb], bd1x); atomicAdd(&bwd_s[1][jb + 1], bd1y);
    atomicAdd(&bwd_s[1][jb + 2], bd1z); atomicAdd(&bwd_s[1][jb + 3], bd1w);
    atomicAdd(&bwd_s[2][jb], bd2x); atomicAdd(&bwd_s[2][jb + 1], bd2y);
    atomicAdd(&bwd_s[2][jb + 2], bd2z); atomicAdd(&bwd_s[2][jb + 3], bd2w);
    atomicAdd(&bwd_s[3][jb], bd3x); atomicAdd(&bwd_s[3][jb + 1], bd3y);
    atomicAdd(&bwd_s[3][jb + 2], bd3z); atomicAdd(&bwd_s[3][jb + 3], bd3w);
    __syncthreads();
    for (int e = tid; e < Rc * CHR; e += 256) {
        int r = e >> 7, i = e & (CHR - 1);
        g_fwd[((size_t)b * Rc + r) * Mc + i0 + i] = fwd_s[r][i];
    }
    for (int e = tid; e < Rc * Mc; e += 256) {
        int r = e >> 9, m = e & 511;
        g_bwdp[(((size_t)c * Bc + b) * Rc + r) * Mc + m] = bwd_s[r][m];
    }
}

// ---------------- K9: read-mode mix + read vectors ----------------
__global__ __launch_bounds__(512) void k9_out(const float* __restrict__ mem,
                                              float* __restrict__ out) {
    int b = blockIdx.x;
    int tid = threadIdx.x;
    int q = tid >> 7, wt = tid & 127;
    __shared__ float rwn[Rc][Mc];
    __shared__ float ww_s[Mc];
    __shared__ float ms[Rc][3];
    __shared__ float part[4][Rc][Wc];
    if (tid < Rc) {
        float a0 = g_rm[b * 12 + tid * 3 + 0];
        float a1 = g_rm[b * 12 + tid * 3 + 1];
        float a2 = g_rm[b * 12 + tid * 3 + 2];
        float mx = fmaxf(a0, fmaxf(a1, a2));
        float e0 = expf(a0 - mx), e1 = expf(a1 - mx), e2 = expf(a2 - mx);
        float s = e0 + e1 + e2;
        ms[tid][0] = e0 / s; ms[tid][1] = e1 / s; ms[tid][2] = e2 / s;
    }
    for (int m = tid; m < Mc; m += 512) ww_s[m] = g_ww[b * Mc + m];
    __syncthreads();
    for (int e = tid; e < Rc * Mc; e += 512) {
        int r = e >> 9, m = e & 511;
        size_t i = ((size_t)b * Rc + r) * Mc + m;
        float bsum = 0.f;
#pragma unroll
        for (int cch = 0; cch < NCH; cch++)
            bsum += g_bwdp[(((size_t)cch * Bc + b) * Rc + r) * Mc + m];
        rwn[r][m] = ms[r][0] * bsum + ms[r][1] * g_fwd[i] + ms[r][2] * g_cw[i];
    }
    __syncthreads();
    float evw = g_ev[b * Wc + wt], wvw = g_wv[b * Wc + wt];
    float a0 = 0.f, a1 = 0.f, a2 = 0.f, a3 = 0.f;
    const float* mb = mem + (size_t)b * Mc * Wc;
#pragma unroll 4
    for (int m = q * 128; m < (q + 1) * 128; m++) {
        float x = mb[(size_t)m * Wc + wt];
        float t = ww_s[m];
        float nm = fmaf(x, 1.f - t * evw, t * wvw);
        a0 = fmaf(rwn[0][m], nm, a0);
        a1 = fmaf(rwn[1][m], nm, a1);
        a2 = fmaf(rwn[2][m], nm, a2);
        a3 = fmaf(rwn[3][m], nm, a3);
    }
    part[q][0][wt] = a0; part[q][1][wt] = a1; part[q][2][wt] = a2; part[q][3][wt] = a3;
    __syncthreads();
    if (q == 0) {
#pragma unroll
        for (int r = 0; r < Rc; r++)
            out[((size_t)b * Rc + r) * Wc + wt] =
                part[0][r][wt] + part[1][r][wt] + part[2][r][wt] + part[3][r][wt];
    }
}

// ---------------- launch ----------------
extern "C" void kernel_launch(void* const* d_in, const int* in_sizes, int n_in,
                              void* d_out, int out_size) {
    const float* x        = (const float*)d_in[0];
    const float* memory   = (const float*)d_in[1];
    const float* link     = (const float*)d_in[2];
    const float* prec     = (const float*)d_in[3];
    const float* rw_old   = (const float*)d_in[4];
    const float* wwts     = (const float*)d_in[5];
    const float* usage_v  = (const float*)d_in[6];

    WPtrs p;
    for (int s = 0; s < 10; s++) {
        p.W[s]   = (const float*)d_in[7 + 2 * s];
        p.bia[s] = (const float*)d_in[8 + 2 * s];
    }
    float* out = (float*)d_out;

    k0_concat<<<NOUT, 256>>>(p);
    k1_gemm<<<dim3((NOUT + 31) / 32, Bc / 32), dim3(16, 16)>>>(x);
    k3_alloc<<<Bc, 512>>>(usage_v, wwts, rw_old);
    k4_mstats<<<(Bc * Mc) / 8, 256>>>(memory);
    k5_ww<<<Bc, 512>>>();
    k6_nstats<<<(Bc * Mc) / 8, 256>>>(memory);
    k7_cw<<<Bc * Rc, 512>>>();
    k8_link<<<dim3(NCH, Bc), 256>>>(link, prec, rw_old);
    k9_out<<<Bc, 512>>>(memory, out);
}